// round 1
// baseline (speedup 1.0000x reference)
#include <cuda_runtime.h>
#include <cuda_bf16.h>
#include <math.h>

// ============================================================================
// MLA prefill (weight-absorbed, causal) — round 1: fp32 SIMT GEMM baseline.
//
// Decomposition (mathematically identical to reference, cheaper):
//   latents[b,s,c]   = sum_m x[b,s,m] * Wd[c,m]                      (G1, NT)
//   q[b,s,hd]        = sum_m x[b,s,m] * Wq[hd,m]                     (G2, NT)
//   q_lat[b,h,s,c]   = sum_d q[b,s,h*128+d] * Wuk[h*128+d,c]        (G3, NN)
//   scores[b,h,s,t]  = sum_c q_lat * latents / sqrt(128), t<=s      (G4, NT, causal-skip)
//   attn             = softmax over t<=s, zeros to next 128 boundary (G5)
//   ctx[b,h,s,c]     = sum_t attn * latents[b,t,c], K_eff per tile  (G6, NN)
//   v[b,s,h*128+d]   = sum_c ctx[b,h,s,c] * Wuv[h*128+d,c]          (G7, NT)
//   out[b,s,m]       = sum_hd v[b,s,hd] * Wo[m,hd]                   (G8, NT)
// ============================================================================

#define SB   2
#define SEQL 2048
#define DMODEL 2048
#define CLAT 512
#define NH   16
#define DHD  128
#define HDTOT 2048   // NH*DHD

// ---------------------------------------------------------------------------
// Scratch (static device globals; allocation at module load is permitted)
// ---------------------------------------------------------------------------
__device__ float g_latents[(size_t)SB * SEQL * CLAT];          //   8 MB
__device__ float g_q      [(size_t)SB * SEQL * HDTOT];         //  32 MB
__device__ float g_qlat   [(size_t)SB * NH * SEQL * CLAT];     // 128 MB
__device__ float g_scores [(size_t)SB * NH * SEQL * SEQL];     // 512 MB
__device__ float g_ctx    [(size_t)SB * NH * SEQL * CLAT];     // 128 MB
__device__ float g_v      [(size_t)SB * SEQL * HDTOT];         //  32 MB

// ---------------------------------------------------------------------------
// Generic tiled fp32 GEMM.  C[M,N] = alpha * A[M,K] @ op(B)
//   MODE 0: plain (no batch offset). B is [N,K] (NT).
//   MODE 1: q_lat:   z=(b,h). A=q(+col h*128), B=Wuk[h] [K,N] (NN), C=q_lat[z]
//   MODE 2: scores:  z=(b,h). A=q_lat[z], B=latents[b] [N,K] (NT), C=scores[z];
//                    causal: skip tiles with bn > bm.
//   MODE 3: ctx:     z=(b,h). A=attn[z], B=latents[b] [K,N] (NN), C=ctx[z];
//                    K_eff = (bm+1)*BM.
//   MODE 4: v:       z=(b,h). A=ctx[z], B=Wuv[h] [N,K] (NT), C=v(+col h*128)
// All M,N multiples of 128 and K multiples of 16: no boundary predicates.
// ---------------------------------------------------------------------------
#define BM 128
#define BN 128
#define BK 16

template<int MODE>
__global__ void __launch_bounds__(256, 2)
gemm_kernel(const float* __restrict__ A, const float* __restrict__ B,
            float* __restrict__ C,
            int M, int N, int K, int lda, int ldb, int ldc, float alpha)
{
    constexpr bool BT = (MODE != 1 && MODE != 3);   // true: B is [N,K] row-major

    const int bn = blockIdx.x;
    const int bm = blockIdx.y;
    const int z  = blockIdx.z;

    if (MODE == 2 && bn > bm) return;   // causal: tile entirely above diagonal

    long long aoff = 0, boff = 0, coff = 0;
    if (MODE == 1) {
        int b = z >> 4, h = z & 15;
        aoff = (long long)b * SEQL * HDTOT + (long long)h * DHD;
        boff = (long long)h * DHD * CLAT;
        coff = (long long)z * SEQL * CLAT;
    } else if (MODE == 2) {
        aoff = (long long)z * SEQL * CLAT;
        boff = (long long)(z >> 4) * SEQL * CLAT;
        coff = (long long)z * SEQL * SEQL;
    } else if (MODE == 3) {
        aoff = (long long)z * SEQL * SEQL;
        boff = (long long)(z >> 4) * SEQL * CLAT;
        coff = (long long)z * SEQL * CLAT;
    } else if (MODE == 4) {
        int b = z >> 4, h = z & 15;
        aoff = (long long)z * SEQL * CLAT;
        boff = (long long)h * DHD * CLAT;
        coff = (long long)b * SEQL * HDTOT + (long long)h * DHD;
    }

    int Keff = K;
    if (MODE == 3) Keff = min(K, (bm + 1) * BM);

    const float* Ab = A + aoff + (long long)bm * BM * lda;
    const float* Bb;
    if (BT) Bb = B + boff + (long long)bn * BN * ldb;
    else    Bb = B + boff + bn * BN;
    float* Cb = C + coff + (long long)bm * BM * ldc + (long long)bn * BN;

    __shared__ float As[BK][BM];
    __shared__ float Bs[BK][BN];

    const int tid = threadIdx.x;
    const int tx = tid & 15;        // 0..15 -> N
    const int ty = tid >> 4;        // 0..15 -> M

    float acc[8][8];
#pragma unroll
    for (int i = 0; i < 8; i++)
#pragma unroll
        for (int j = 0; j < 8; j++) acc[i][j] = 0.f;

    for (int k0 = 0; k0 < Keff; k0 += BK) {
        // ---- load A tile: 128 rows x 16 K, K-contiguous, 512 float4 total
#pragma unroll
        for (int i = 0; i < 2; i++) {
            int f  = tid + i * 256;
            int r  = f >> 2;
            int c4 = (f & 3) * 4;
            float4 v = *reinterpret_cast<const float4*>(Ab + (long long)r * lda + k0 + c4);
            As[c4 + 0][r] = v.x; As[c4 + 1][r] = v.y;
            As[c4 + 2][r] = v.z; As[c4 + 3][r] = v.w;
        }
        // ---- load B tile
        if (BT) {
#pragma unroll
            for (int i = 0; i < 2; i++) {
                int f  = tid + i * 256;
                int r  = f >> 2;
                int c4 = (f & 3) * 4;
                float4 v = *reinterpret_cast<const float4*>(Bb + (long long)r * ldb + k0 + c4);
                Bs[c4 + 0][r] = v.x; Bs[c4 + 1][r] = v.y;
                Bs[c4 + 2][r] = v.z; Bs[c4 + 3][r] = v.w;
            }
        } else {
#pragma unroll
            for (int i = 0; i < 2; i++) {
                int f  = tid + i * 256;
                int r  = f >> 5;          // 0..15 K-row
                int c4 = (f & 31) * 4;    // 0..124 N-col
                float4 v = *reinterpret_cast<const float4*>(Bb + (long long)(k0 + r) * ldb + c4);
                *reinterpret_cast<float4*>(&Bs[r][c4]) = v;
            }
        }
        __syncthreads();

#pragma unroll
        for (int k = 0; k < BK; k++) {
            float4 a0 = *reinterpret_cast<const float4*>(&As[k][ty * 8]);
            float4 a1 = *reinterpret_cast<const float4*>(&As[k][ty * 8 + 4]);
            float4 b0 = *reinterpret_cast<const float4*>(&Bs[k][tx * 8]);
            float4 b1 = *reinterpret_cast<const float4*>(&Bs[k][tx * 8 + 4]);
            float ar[8] = {a0.x, a0.y, a0.z, a0.w, a1.x, a1.y, a1.z, a1.w};
            float br[8] = {b0.x, b0.y, b0.z, b0.w, b1.x, b1.y, b1.z, b1.w};
#pragma unroll
            for (int i = 0; i < 8; i++)
#pragma unroll
                for (int j = 0; j < 8; j++)
                    acc[i][j] = fmaf(ar[i], br[j], acc[i][j]);
        }
        __syncthreads();
    }

    // ---- store
#pragma unroll
    for (int i = 0; i < 8; i++) {
        float* crow = Cb + (long long)(ty * 8 + i) * ldc + tx * 8;
#pragma unroll
        for (int j = 0; j < 8; j += 4) {
            float4 v = make_float4(acc[i][j] * alpha, acc[i][j + 1] * alpha,
                                   acc[i][j + 2] * alpha, acc[i][j + 3] * alpha);
            *reinterpret_cast<float4*>(crow + j) = v;
        }
    }
}

// ---------------------------------------------------------------------------
// Causal row softmax, in place over g_scores.
// One warp per row r = z*SEQL + s. Reads t in [0, s]; writes probabilities
// there and zeros in (s, next multiple of 128) so G6 can use K_eff tiles.
// ---------------------------------------------------------------------------
__global__ void softmax_kernel(float* __restrict__ scores)
{
    const int warp = threadIdx.x >> 5;
    const int lane = threadIdx.x & 31;
    const long long r = (long long)blockIdx.x * (blockDim.x >> 5) + warp;
    const int s   = (int)(r & (SEQL - 1));
    const int len = s + 1;
    float* row = scores + r * SEQL;

    float mx = -INFINITY;
    for (int j = lane; j < len; j += 32) mx = fmaxf(mx, row[j]);
#pragma unroll
    for (int o = 16; o > 0; o >>= 1) mx = fmaxf(mx, __shfl_xor_sync(0xffffffffu, mx, o));

    float sum = 0.f;
    for (int j = lane; j < len; j += 32) {
        float e = __expf(row[j] - mx);
        row[j] = e;
        sum += e;
    }
#pragma unroll
    for (int o = 16; o > 0; o >>= 1) sum += __shfl_xor_sync(0xffffffffu, sum, o);

    const float inv = 1.0f / sum;
    for (int j = lane; j < len; j += 32) row[j] *= inv;

    const int zend = ((s >> 7) + 1) << 7;   // next multiple of 128 past s
    for (int j = len + lane; j < zend; j += 32) row[j] = 0.f;
}

// ---------------------------------------------------------------------------
// Launch
// ---------------------------------------------------------------------------
extern "C" void kernel_launch(void* const* d_in, const int* in_sizes, int n_in,
                              void* d_out, int out_size)
{
    const float* x   = (const float*)d_in[0];
    const float* Wd  = (const float*)d_in[1];
    const float* Wuk = (const float*)d_in[2];
    const float* Wuv = (const float*)d_in[3];
    const float* Wq  = (const float*)d_in[4];
    const float* Wo  = (const float*)d_in[5];
    float* out = (float*)d_out;

    float *lat, *q, *qlat, *sc, *ctx, *v;
    cudaGetSymbolAddress((void**)&lat,  g_latents);
    cudaGetSymbolAddress((void**)&q,    g_q);
    cudaGetSymbolAddress((void**)&qlat, g_qlat);
    cudaGetSymbolAddress((void**)&sc,   g_scores);
    cudaGetSymbolAddress((void**)&ctx,  g_ctx);
    cudaGetSymbolAddress((void**)&v,    g_v);

    const int MROWS = SB * SEQL;   // 4096
    const dim3 blk(256);
    const float inv_sqrt_dh = 0.08838834764831845f;   // 1/sqrt(128)

    // G1: latents = x @ Wd^T        [4096,512] K=2048
    gemm_kernel<0><<<dim3(CLAT / BN, MROWS / BM, 1), blk>>>(
        x, Wd, lat, MROWS, CLAT, DMODEL, DMODEL, DMODEL, CLAT, 1.f);

    // G2: q = x @ Wq^T              [4096,2048] K=2048
    gemm_kernel<0><<<dim3(HDTOT / BN, MROWS / BM, 1), blk>>>(
        x, Wq, q, MROWS, HDTOT, DMODEL, DMODEL, DMODEL, HDTOT, 1.f);

    // G3: q_lat[z] = q_h @ Wuk_h    [2048,512] K=128, z = b*16+h
    gemm_kernel<1><<<dim3(CLAT / BN, SEQL / BM, SB * NH), blk>>>(
        q, Wuk, qlat, SEQL, CLAT, DHD, HDTOT, CLAT, CLAT, 1.f);

    // G4: scores[z] = q_lat[z] @ latents[b]^T / sqrt(128), causal tiles only
    gemm_kernel<2><<<dim3(SEQL / BN, SEQL / BM, SB * NH), blk>>>(
        qlat, lat, sc, SEQL, SEQL, CLAT, CLAT, CLAT, SEQL, inv_sqrt_dh);

    // G5: softmax rows (one warp per row)
    {
        long long rows = (long long)SB * NH * SEQL;     // 65536
        softmax_kernel<<<(unsigned)(rows / 8), 256>>>(sc);
    }

    // G6: ctx[z] = attn[z] @ latents[b]   [2048,512], K_eff per row tile
    gemm_kernel<3><<<dim3(CLAT / BN, SEQL / BM, SB * NH), blk>>>(
        sc, lat, ctx, SEQL, CLAT, SEQL, SEQL, CLAT, CLAT, 1.f);

    // G7: v_h = ctx[z] @ Wuv_h^T    [2048,128] K=512
    gemm_kernel<4><<<dim3(DHD / BN, SEQL / BM, SB * NH), blk>>>(
        ctx, Wuv, v, SEQL, DHD, CLAT, CLAT, CLAT, HDTOT, 1.f);

    // G8: out = v @ Wo^T            [4096,2048] K=2048
    gemm_kernel<0><<<dim3(DMODEL / BN, MROWS / BM, 1), blk>>>(
        v, Wo, out, MROWS, DMODEL, HDTOT, HDTOT, HDTOT, DMODEL, 1.f);
}

// round 7
// speedup vs baseline: 2.2619x; 2.2619x over previous
#include <cuda_runtime.h>
#include <cuda_fp16.h>
#include <math.h>
#include <stdint.h>

// ============================================================================
// MLA prefill — round 6: fp16 split-precision (hi+lo, 3-pass) mma.sync GEMMs.
// (Round-5 resubmit: broker container flake, kernel never executed.)
// tcgen05 unavailable (harness targets compute_100); tf32 single-pass failed
// accuracy (3.5e-3). fp16 hi/lo split gives ~22 mantissa bits per product at
// 2x the per-instruction rate of tf32.
//
//   G1: latents = x @ Wd^T                       [4096, 512]  K=2048  (NT)
//   T1: latT[b] = latents[b]^T ; T2: WukT[h] = Wuk[h]^T
//   G2: q = x @ Wq^T                             [4096,2048]  K=2048  (NT)
//   G3: q_lat[z] = q_h @ WukT[h]^T               [2048, 512]  K=128   (NT)
//   G4: scores[z] = q_lat @ latents[b]^T /sqrt   [2048,2048]  K=512   (NT, causal)
//   G5: softmax rows (t <= s), zero-fill to tile boundary
//   G6: ctx[z] = attn @ latT[b]^T                [2048, 512]  K=(bm+1)*128
//   G7: v_h = ctx @ Wuv_h^T                      [2048, 128]  K=512   (NT)
//   G8: out = v @ Wo^T                           [4096,2048]  K=2048  (NT)
// ============================================================================

#define SB     2
#define SEQL   2048
#define DMODEL 2048
#define CLAT   512
#define NH     16
#define DHD    128
#define HDTOT  2048

// ---------------- scratch ----------------
__device__ float g_latents[(size_t)SB * SEQL * CLAT];        //   8 MB
__device__ float g_latT   [(size_t)SB * CLAT * SEQL];        //   8 MB
__device__ float g_wukT   [(size_t)NH * CLAT * DHD];         //   4 MB
__device__ float g_q      [(size_t)SB * SEQL * HDTOT];       //  32 MB
__device__ float g_qlat   [(size_t)SB * NH * SEQL * CLAT];   // 128 MB
__device__ float g_scores [(size_t)SB * NH * SEQL * SEQL];   // 512 MB
__device__ float g_ctx    [(size_t)SB * NH * SEQL * CLAT];   // 128 MB
__device__ float g_v      [(size_t)SB * SEQL * HDTOT];       //  32 MB

#define BM 128
#define BN 128
#define BK 16
#define PAD 24     // smem row pitch in floats (16 data + 8 pad): conflict-free float2

// m16n8k16 fp16 mma, fp32 accumulate.
static __device__ __forceinline__ void mma_16816(float* d, const uint32_t* a,
                                                 const uint32_t* b) {
    asm volatile(
        "mma.sync.aligned.m16n8k16.row.col.f32.f16.f16.f32 "
        "{%0,%1,%2,%3}, {%4,%5,%6,%7}, {%8,%9}, {%0,%1,%2,%3};"
        : "+f"(d[0]), "+f"(d[1]), "+f"(d[2]), "+f"(d[3])
        : "r"(a[0]), "r"(a[1]), "r"(a[2]), "r"(a[3]), "r"(b[0]), "r"(b[1]));
}

// Split a float2 into fp16 hi + fp16 residual lo (packed half2 bit patterns).
static __device__ __forceinline__ void split2(float2 f, uint32_t& hi, uint32_t& lo) {
    __half2 h = __floats2half2_rn(f.x, f.y);
    float2 hf = __half22float2(h);
    __half2 l = __floats2half2_rn(f.x - hf.x, f.y - hf.y);
    hi = *reinterpret_cast<uint32_t*>(&h);
    lo = *reinterpret_cast<uint32_t*>(&l);
}

// Prefetch one 128x16 f32 tile into padded smem via cp.async (2 chunks/thread).
static __device__ __forceinline__ void prefetch_tile(float* s, const float* gptr,
                                                     int ld, int tid) {
#pragma unroll
    for (int i = 0; i < 2; i++) {
        int idx = tid + i * 256;
        int r = idx >> 2;
        int c = (idx & 3) * 4;
        unsigned dst = (unsigned)__cvta_generic_to_shared(s + r * PAD + c);
        asm volatile("cp.async.cg.shared.global [%0], [%1], 16;"
                     :: "r"(dst), "l"(gptr + (long long)r * ld + c));
    }
}

// ---------------------------------------------------------------------------
// GEMM: C[128m,128n] = alpha * A @ B^T, A[M,K], B[N,K] row-major, fp32 in/out.
// MODE 0: plain. 1: G3. 2: G4 (causal skip). 3: G6 (K_eff). 4: G7.
// 256 threads = 8 warps (2m x 4n); warp tile 64x32 = 4x4 m16n8k16 atoms.
// ---------------------------------------------------------------------------
template<int MODE>
__global__ void __launch_bounds__(256)
mma_gemm(const float* __restrict__ A, const float* __restrict__ B, float* __restrict__ C,
         int K, int lda, int ldb, int ldc, float alpha)
{
    const int bn = blockIdx.x;
    const int bm = blockIdx.y;
    const int z  = blockIdx.z;

    if (MODE == 2 && bn > bm) return;      // causal: whole block above diagonal

    long long aoff = 0, boff = 0, coff = 0;
    if (MODE == 1) {
        int b = z >> 4, h = z & 15;
        aoff = (long long)b * SEQL * HDTOT + (long long)h * DHD;
        boff = (long long)h * CLAT * DHD;
        coff = (long long)z * SEQL * CLAT;
    } else if (MODE == 2) {
        aoff = (long long)z * SEQL * CLAT;
        boff = (long long)(z >> 4) * SEQL * CLAT;
        coff = (long long)z * SEQL * SEQL;
    } else if (MODE == 3) {
        aoff = (long long)z * SEQL * SEQL;
        boff = (long long)(z >> 4) * CLAT * SEQL;
        coff = (long long)z * SEQL * CLAT;
    } else if (MODE == 4) {
        int b = z >> 4, h = z & 15;
        aoff = (long long)z * SEQL * CLAT;
        boff = (long long)h * DHD * CLAT;
        coff = (long long)b * SEQL * HDTOT + (long long)h * DHD;
    }

    const int Keff = (MODE == 3) ? min(K, (bm + 1) * BM) : K;
    const int nkt = Keff / BK;

    const float* Ab = A + aoff + (long long)bm * BM * lda;
    const float* Bb = B + boff + (long long)bn * BN * ldb;
    float* Cb = C + coff + (long long)bm * BM * ldc + (long long)bn * BN;

    __shared__ float As[2][BM * PAD];
    __shared__ float Bs[2][BN * PAD];

    const int tid  = threadIdx.x;
    const int lane = tid & 31;
    const int w    = tid >> 5;
    const int mo = (w >> 2) * 64;          // warp m offset (0/64)
    const int no = (w & 3) * 32;           // warp n offset (0/32/64/96)
    const int g  = lane >> 2;              // group 0..7
    const int t  = lane & 3;               // thread-in-group 0..3

    float acc[4][4][4];
#pragma unroll
    for (int mt = 0; mt < 4; mt++)
#pragma unroll
        for (int nt = 0; nt < 4; nt++)
#pragma unroll
            for (int e = 0; e < 4; e++) acc[mt][nt][e] = 0.f;

    // prologue
    prefetch_tile(As[0], Ab, lda, tid);
    prefetch_tile(Bs[0], Bb, ldb, tid);
    asm volatile("cp.async.commit_group;");

    for (int kt = 0; kt < nkt; ++kt) {
        const int buf = kt & 1;
        if (kt + 1 < nkt) {
            prefetch_tile(As[buf ^ 1], Ab + (long long)(kt + 1) * BK, lda, tid);
            prefetch_tile(Bs[buf ^ 1], Bb + (long long)(kt + 1) * BK, ldb, tid);
            asm volatile("cp.async.commit_group;");
            asm volatile("cp.async.wait_group 1;");
        } else {
            asm volatile("cp.async.wait_group 0;");
        }
        __syncthreads();

        const float* Asb = As[buf];
        const float* Bsb = Bs[buf];

        // --- fragments: A rows g/g+8 at k = 2t,2t+1 and 2t+8,2t+9
        uint32_t ah[4][4], al[4][4], bh[4][2], bl[4][2];
#pragma unroll
        for (int mt = 0; mt < 4; mt++) {
            const float* ap = Asb + (mo + mt * 16 + g) * PAD + 2 * t;
            split2(*reinterpret_cast<const float2*>(ap),               ah[mt][0], al[mt][0]);
            split2(*reinterpret_cast<const float2*>(ap + 8 * PAD),     ah[mt][1], al[mt][1]);
            split2(*reinterpret_cast<const float2*>(ap + 8),           ah[mt][2], al[mt][2]);
            split2(*reinterpret_cast<const float2*>(ap + 8 * PAD + 8), ah[mt][3], al[mt][3]);
        }
#pragma unroll
        for (int nt = 0; nt < 4; nt++) {
            const float* bp = Bsb + (no + nt * 8 + g) * PAD + 2 * t;
            split2(*reinterpret_cast<const float2*>(bp),     bh[nt][0], bl[nt][0]);
            split2(*reinterpret_cast<const float2*>(bp + 8), bh[nt][1], bl[nt][1]);
        }

        // --- 3-pass split-precision mma: hi*hi + hi*lo + lo*hi
#pragma unroll
        for (int mt = 0; mt < 4; mt++)
#pragma unroll
            for (int nt = 0; nt < 4; nt++) {
                mma_16816(acc[mt][nt], ah[mt], bh[nt]);
                mma_16816(acc[mt][nt], ah[mt], bl[nt]);
                mma_16816(acc[mt][nt], al[mt], bh[nt]);
            }
        __syncthreads();
    }

    // epilogue: c0/c1 at (g, 2t..2t+1), c2/c3 at (g+8, 2t..2t+1)
#pragma unroll
    for (int mt = 0; mt < 4; mt++) {
        const int r0 = mo + mt * 16 + g;
#pragma unroll
        for (int nt = 0; nt < 4; nt++) {
            const int ccol = no + nt * 8 + 2 * t;
            float2 v0 = make_float2(acc[mt][nt][0] * alpha, acc[mt][nt][1] * alpha);
            float2 v1 = make_float2(acc[mt][nt][2] * alpha, acc[mt][nt][3] * alpha);
            *reinterpret_cast<float2*>(Cb + (long long)r0 * ldc + ccol) = v0;
            *reinterpret_cast<float2*>(Cb + (long long)(r0 + 8) * ldc + ccol) = v1;
        }
    }
}

// ---------------------------------------------------------------------------
// 32x32 shared-tile transpose:  in [z][R][C] -> out [z][C][R]
// ---------------------------------------------------------------------------
__global__ void transpose_kernel(const float* __restrict__ in, float* __restrict__ out,
                                 int R, int Cc)
{
    __shared__ float tsm[32][33];
    const int z = blockIdx.z;
    const int r0 = blockIdx.y * 32, c0 = blockIdx.x * 32;
    const float* I = in + (long long)z * R * Cc;
    float* O = out + (long long)z * R * Cc;
    const int tx = threadIdx.x, ty = threadIdx.y;
#pragma unroll
    for (int i = 0; i < 32; i += 8)
        tsm[ty + i][tx] = I[(long long)(r0 + ty + i) * Cc + c0 + tx];
    __syncthreads();
#pragma unroll
    for (int i = 0; i < 32; i += 8)
        O[(long long)(c0 + ty + i) * R + r0 + tx] = tsm[tx][ty + i];
}

// ---------------------------------------------------------------------------
// Causal row softmax (one warp per row), zero-fill to next 128 boundary.
// ---------------------------------------------------------------------------
__global__ void softmax_kernel(float* __restrict__ scores)
{
    const int warp = threadIdx.x >> 5;
    const int lane = threadIdx.x & 31;
    const long long r = (long long)blockIdx.x * (blockDim.x >> 5) + warp;
    const int s = (int)(r & (SEQL - 1));
    const int len = s + 1;
    float* row = scores + r * SEQL;

    float mx = -INFINITY;
    for (int j = lane; j < len; j += 32) mx = fmaxf(mx, row[j]);
#pragma unroll
    for (int o = 16; o > 0; o >>= 1) mx = fmaxf(mx, __shfl_xor_sync(0xffffffffu, mx, o));

    float sum = 0.f;
    for (int j = lane; j < len; j += 32) {
        float e = __expf(row[j] - mx);
        row[j] = e;
        sum += e;
    }
#pragma unroll
    for (int o = 16; o > 0; o >>= 1) sum += __shfl_xor_sync(0xffffffffu, sum, o);

    const float inv = 1.0f / sum;
    for (int j = lane; j < len; j += 32) row[j] *= inv;

    const int zend = ((s >> 7) + 1) << 7;
    for (int j = len + lane; j < zend; j += 32) row[j] = 0.f;
}

// ---------------------------------------------------------------------------
extern "C" void kernel_launch(void* const* d_in, const int* in_sizes, int n_in,
                              void* d_out, int out_size)
{
    const float* x   = (const float*)d_in[0];
    const float* Wd  = (const float*)d_in[1];
    const float* Wuk = (const float*)d_in[2];
    const float* Wuv = (const float*)d_in[3];
    const float* Wq  = (const float*)d_in[4];
    const float* Wo  = (const float*)d_in[5];
    float* out = (float*)d_out;

    float *lat, *latT, *wukT, *q, *qlat, *sc, *ctx, *v;
    cudaGetSymbolAddress((void**)&lat,  g_latents);
    cudaGetSymbolAddress((void**)&latT, g_latT);
    cudaGetSymbolAddress((void**)&wukT, g_wukT);
    cudaGetSymbolAddress((void**)&q,    g_q);
    cudaGetSymbolAddress((void**)&qlat, g_qlat);
    cudaGetSymbolAddress((void**)&sc,   g_scores);
    cudaGetSymbolAddress((void**)&ctx,  g_ctx);
    cudaGetSymbolAddress((void**)&v,    g_v);

    const int MROWS = SB * SEQL;  // 4096
    const dim3 blk(256);
    const float inv_sqrt_dh = 0.08838834764831845f;

    // G1: latents = x @ Wd^T
    mma_gemm<0><<<dim3(CLAT / BN, MROWS / BM, 1), blk>>>(
        x, Wd, lat, DMODEL, DMODEL, DMODEL, CLAT, 1.f);

    // T1/T2: transposes
    transpose_kernel<<<dim3(CLAT / 32, SEQL / 32, SB), dim3(32, 8)>>>(lat, latT, SEQL, CLAT);
    transpose_kernel<<<dim3(CLAT / 32, DHD / 32, NH), dim3(32, 8)>>>(Wuk, wukT, DHD, CLAT);

    // G2: q = x @ Wq^T
    mma_gemm<0><<<dim3(HDTOT / BN, MROWS / BM, 1), blk>>>(
        x, Wq, q, DMODEL, DMODEL, DMODEL, HDTOT, 1.f);

    // G3: q_lat[z] = q_h @ WukT[h]^T   (K = 128)
    mma_gemm<1><<<dim3(CLAT / BN, SEQL / BM, SB * NH), blk>>>(
        q, wukT, qlat, DHD, HDTOT, DHD, CLAT, 1.f);

    // G4: scores = q_lat @ latents^T / sqrt(dh), causal tiles only
    mma_gemm<2><<<dim3(SEQL / BN, SEQL / BM, SB * NH), blk>>>(
        qlat, lat, sc, CLAT, CLAT, CLAT, SEQL, inv_sqrt_dh);

    // G5: softmax
    softmax_kernel<<<(unsigned)((long long)SB * NH * SEQL / 8), 256>>>(sc);

    // G6: ctx = attn @ latT^T  (K_eff per row tile)
    mma_gemm<3><<<dim3(CLAT / BN, SEQL / BM, SB * NH), blk>>>(
        sc, latT, ctx, SEQL, SEQL, SEQL, CLAT, 1.f);

    // G7: v_h = ctx @ Wuv_h^T
    mma_gemm<4><<<dim3(DHD / BN, SEQL / BM, SB * NH), blk>>>(
        ctx, Wuv, v, CLAT, CLAT, CLAT, HDTOT, 1.f);

    // G8: out = v @ Wo^T
    mma_gemm<0><<<dim3(DMODEL / BN, MROWS / BM, 1), blk>>>(
        v, Wo, out, HDTOT, HDTOT, HDTOT, DMODEL, 1.f);
}